// round 12
// baseline (speedup 1.0000x reference)
#include <cuda_runtime.h>
#include <math.h>

// ---------------- problem dims ----------------
#define EPSV 1e-5f
#define B 4
#define C 64           // input channels
#define H 128
#define W 128
#define HW (H*W)       // 16384
#define CMID 64        // compressed channels
#define O 100          // encoder output channels (25 kernels * 4 quadrants)
#define OP 128         // padded O for clean tiling
#define NTAP 9

// ---------------- device scratch (no allocation allowed) ----------------
__device__ float g_M[B*CMID*HW];        // compressed feature map  (16.8 MB)
__device__ float g_E[B*O*HW];           // encoder output          (26.2 MB)
__device__ float g_wenc[NTAP*CMID*OP];  // scaled, padded, transposed enc weights [tap][cm][o]
__device__ float g_benc[OP];            // folded bias+BN

// ---------------- packed fp32x2 FMA (Blackwell, PTX-only) ----------------
__device__ __forceinline__ void ffma2(float2& d, float2 a, float2 b) {
    asm("fma.rn.f32x2 %0, %1, %2, %0;"
        : "+l"(reinterpret_cast<unsigned long long&>(d))
        : "l"(reinterpret_cast<unsigned long long&>(a)),
          "l"(reinterpret_cast<unsigned long long&>(b)));
}

// =====================================================================
// K0: prep — fold enc BN into weights, pad O 100->128, layout [tap][cm][o]
// =====================================================================
__global__ void k_prep(const float* __restrict__ enc_w, const float* __restrict__ enc_b,
                       const float* __restrict__ eg, const float* __restrict__ ebt,
                       const float* __restrict__ em, const float* __restrict__ ev) {
    int gid = blockIdx.x * blockDim.x + threadIdx.x;
    if (gid < NTAP*CMID*OP) {
        int o   = gid & (OP-1);
        int cm  = (gid >> 7) & 63;
        int tap = gid >> 13;
        float v = 0.f;
        if (o < O) {
            float inv = eg[o] * rsqrtf(ev[o] + EPSV);
            v = enc_w[o*576 + cm*9 + tap] * inv;   // enc_w is [O][CMID][3][3]
        }
        g_wenc[gid] = v;
    }
    if (gid < OP) {
        float v = 0.f;
        if (gid < O) {
            float inv = eg[gid] * rsqrtf(ev[gid] + EPSV);
            v = enc_b[gid]*inv + ebt[gid] - em[gid]*inv;
        }
        g_benc[gid] = v;
    }
}

// =====================================================================
// K1: compress — 1x1 conv (64x64 GEMM per pixel) + BN + ReLU -> g_M
// one thread per pixel, 64 accumulators paired into 32 f32x2
// =====================================================================
__global__ __launch_bounds__(256) void k_compress(
        const float* __restrict__ X, const float* __restrict__ cw,
        const float* __restrict__ cg, const float* __restrict__ cb,
        const float* __restrict__ cmu, const float* __restrict__ cv) {
    __shared__ float sw1[C*CMID];   // [c][cm] transposed + BN folded
    __shared__ float sb1[CMID];
    int tid = threadIdx.x;
    for (int i = tid; i < C*CMID; i += 256) {
        int cmi = i & 63, c = i >> 6;
        float inv = cg[cmi] * rsqrtf(cv[cmi] + EPSV);
        sw1[i] = cw[cmi*C + c] * inv;
    }
    if (tid < CMID) {
        float inv = cg[tid] * rsqrtf(cv[tid] + EPSV);
        sb1[tid] = cb[tid] - cmu[tid]*inv;
    }
    __syncthreads();

    int gid = blockIdx.x * 256 + tid;     // 0 .. 65535
    int b = gid >> 14, s = gid & (HW-1);
    const float* xp = X + (size_t)b*C*HW + s;

    float2 acc[CMID/2];
#pragma unroll
    for (int j = 0; j < CMID/2; j++) acc[j] = make_float2(0.f, 0.f);

    for (int c = 0; c < C; c++) {
        float xv = xp[c*HW];
        float2 x2 = make_float2(xv, xv);
        const float2* wr = reinterpret_cast<const float2*>(&sw1[c*CMID]);
#pragma unroll
        for (int j = 0; j < CMID/2; j++) ffma2(acc[j], wr[j], x2);
    }

    float* mp = g_M + (size_t)b*CMID*HW + s;
#pragma unroll
    for (int j = 0; j < CMID/2; j++) {
        mp[(2*j  )*HW] = fmaxf(acc[j].x + sb1[2*j  ], 0.f);
        mp[(2*j+1)*HW] = fmaxf(acc[j].y + sb1[2*j+1], 0.f);
    }
}

// =====================================================================
// K2: encode — 3x3 conv as K=576 GEMM (OP=128 x 128 pixels per block)
// tile: 8 rows x 16 cols of low-res pixels; thread = (to 0..15, tp 0..15)
// thread computes 8 o's (4 f32x2 pairs) x 8 pixels (rows) = 64 results
// cm processed in 2 halves of 32 so static smem stays under 48KB
// =====================================================================
#define TH 8
#define TW 16
#define HALFC 32
__global__ __launch_bounds__(256, 2) void k_encode() {
    __shared__ float sM[HALFC*10*18];   // halo tile: 32 ch x (8+2) x (16+2)  (23 KB)
    __shared__ float sW[HALFC*OP];      // weights for one tap, 32 cm x 128 o (16 KB)

    int tid = threadIdx.x;
    int to = tid >> 4, tp = tid & 15;
    int b   = blockIdx.z;
    int yl0 = blockIdx.y * TH;
    int xl0 = blockIdx.x * TW;

    float2 acc[4][8];
#pragma unroll
    for (int u = 0; u < 4; u++)
#pragma unroll
        for (int r = 0; r < 8; r++) acc[u][r] = make_float2(0.f, 0.f);

    for (int half = 0; half < 2; half++) {
        __syncthreads();
        // load M halo tile for this cm half (zero-pad at image borders)
        for (int i = tid; i < HALFC*180; i += 256) {
            int cmL = i / 180;
            int rem = i - cmL*180;
            int rr = rem / 18, cc = rem - rr*18;
            int gy = yl0 + rr - 1, gx = xl0 + cc - 1;
            float v = 0.f;
            if ((unsigned)gy < H && (unsigned)gx < W)
                v = g_M[((size_t)(b*CMID + half*HALFC + cmL) << 14) + gy*W + gx];
            sM[i] = v;
        }
        for (int tap = 0; tap < 9; tap++) {
            __syncthreads();
            const float* wsrc = g_wenc + tap*(CMID*OP) + half*HALFC*OP;
            for (int i = tid; i < HALFC*OP; i += 256) sW[i] = wsrc[i];
            __syncthreads();

            int di = tap / 3, dj = tap - di*3;
            int mo = di*18 + dj + tp;           // + r*18 per pixel row
#pragma unroll 2
            for (int kk = 0; kk < HALFC; kk++) {
                const float* mp = &sM[kk*180 + mo];
                float2 m2[8];
#pragma unroll
                for (int r = 0; r < 8; r++) {
                    float v = mp[r*18];
                    m2[r] = make_float2(v, v);
                }
                const float2* wp = reinterpret_cast<const float2*>(&sW[kk*OP + to*8]);
                float2 w2[4];
#pragma unroll
                for (int u = 0; u < 4; u++) w2[u] = wp[u];
#pragma unroll
                for (int u = 0; u < 4; u++)
#pragma unroll
                    for (int r = 0; r < 8; r++) ffma2(acc[u][r], w2[u], m2[r]);
            }
        }
    }

    // epilogue: add folded bias, store (skip padded o >= 100)
#pragma unroll
    for (int u = 0; u < 4; u++) {
        int o0 = to*8 + 2*u, o1 = o0 + 1;
        float b0 = g_benc[o0], b1 = g_benc[o1];
#pragma unroll
        for (int r = 0; r < 8; r++) {
            int row = yl0 + r;
            if (o0 < O) g_E[((size_t)(b*O + o0) << 14) + row*W + xl0 + tp] = acc[u][r].x + b0;
            if (o1 < O) g_E[((size_t)(b*O + o1) << 14) + row*W + xl0 + tp] = acc[u][r].y + b1;
        }
    }
}

// =====================================================================
// K3: pixel-shuffle + softmax + CARAFE gather
// dilation==scale==2 collapses taps onto the low-res grid:
//   out[b,c,2yl+dy,2xl+dx] = sum_{i,j} softmaxW[b, i*5+j, q=2dy+dx, yl,xl]
//                                      * X[b,c, yl+i-2, xl+j-2]   (0 if OOB)
// block tile: 4 x 16 low-res pixels; X staged in smem (2 halves of 32 ch);
// f32x2 pairs the (dx=0, dx=1) outputs which share every X tap.
// =====================================================================
#define SWS 102   // per-pixel weight stride (pad vs 100: bank-conflict friendly, keeps 8B align)
__global__ __launch_bounds__(256) void k_carafe(const float* __restrict__ X,
                                                float* __restrict__ out) {
    __shared__ float sw[64*SWS];    // softmax weights: [pix][k*4+q]   (25.5 KB)
    __shared__ float sx[32*8*20];   // X halo tile: 32 ch x (4+4) x (16+4) (20 KB)

    int tid = threadIdx.x;
    int b   = blockIdx.z;
    int yl0 = blockIdx.y * 4;
    int xl0 = blockIdx.x * 16;

    // phase 1: softmax over 25 kernel taps, one (pixel, quadrant) per thread
    {
        int pix = tid >> 2, q = tid & 3;
        int prow = pix >> 4, pcol = pix & 15;
        size_t base = ((size_t)(b*O) << 14) + (yl0 + prow)*W + xl0 + pcol;
        float e[25];
        float mx = -1e30f;
#pragma unroll
        for (int k = 0; k < 25; k++) {
            e[k] = g_E[base + (size_t)(4*k + q)*HW];
            mx = fmaxf(mx, e[k]);
        }
        float s = 0.f;
#pragma unroll
        for (int k = 0; k < 25; k++) { e[k] = expf(e[k] - mx); s += e[k]; }
        float inv = 1.f / s;
#pragma unroll
        for (int k = 0; k < 25; k++) sw[pix*SWS + 4*k + q] = e[k]*inv;
    }

    int cgrp = tid >> 4, col = tid & 15;

    for (int half = 0; half < 2; half++) {
        __syncthreads();
        // stage X halo tile for 32 channels
        for (int i = tid; i < 32*160; i += 256) {
            int cL = i / 160;
            int rem = i - cL*160;
            int rr = rem / 20, cc = rem - rr*20;
            int gy = yl0 + rr - 2, gx = xl0 + cc - 2;
            float v = 0.f;
            if ((unsigned)gy < H && (unsigned)gx < W)
                v = X[((size_t)(b*C + half*32 + cL) << 14) + gy*W + gx];
            sx[i] = v;
        }
        __syncthreads();

#pragma unroll
        for (int cq = 0; cq < 2; cq++) {
            int cL = cgrp*2 + cq;
            int c  = half*32 + cL;
#pragma unroll
            for (int rloc = 0; rloc < 4; rloc++) {
                const float* swp = &sw[(rloc*16 + col)*SWS];
                const float* sxp = &sx[cL*160 + rloc*20 + col];
                float2 a0 = make_float2(0.f, 0.f);   // (dy=0, dx=0/1)
                float2 a1 = make_float2(0.f, 0.f);   // (dy=1, dx=0/1)
#pragma unroll
                for (int i5 = 0; i5 < 5; i5++)
#pragma unroll
                    for (int j5 = 0; j5 < 5; j5++) {
                        float xv = sxp[i5*20 + j5];
                        float2 x2 = make_float2(xv, xv);
                        int t4 = (i5*5 + j5)*4;
                        float2 w0 = *reinterpret_cast<const float2*>(&swp[t4]);
                        float2 w1 = *reinterpret_cast<const float2*>(&swp[t4 + 2]);
                        ffma2(a0, w0, x2);
                        ffma2(a1, w1, x2);
                    }
                int y = yl0 + rloc, x = xl0 + col;
                float* op = out + ((size_t)(b*C + c)*(2*H) + 2*y)*(2*W) + 2*x;
                *reinterpret_cast<float2*>(op)          = a0;
                *reinterpret_cast<float2*>(op + 2*W)    = a1;
            }
        }
    }
}

// =====================================================================
// launch
// =====================================================================
extern "C" void kernel_launch(void* const* d_in, const int* in_sizes, int n_in,
                              void* d_out, int out_size) {
    const float* X      = (const float*)d_in[0];
    const float* comp_w = (const float*)d_in[1];
    const float* comp_g = (const float*)d_in[2];
    const float* comp_b = (const float*)d_in[3];
    const float* comp_m = (const float*)d_in[4];
    const float* comp_v = (const float*)d_in[5];
    const float* enc_w  = (const float*)d_in[6];
    const float* enc_b  = (const float*)d_in[7];
    const float* enc_g  = (const float*)d_in[8];
    const float* enc_bt = (const float*)d_in[9];
    const float* enc_m  = (const float*)d_in[10];
    const float* enc_v  = (const float*)d_in[11];
    float* out = (float*)d_out;

    k_prep<<<(NTAP*CMID*OP + 255)/256, 256>>>(enc_w, enc_b, enc_g, enc_bt, enc_m, enc_v);
    k_compress<<<(B*HW)/256, 256>>>(X, comp_w, comp_g, comp_b, comp_m, comp_v);

    dim3 g2(W/TW, H/TH, B);   // (8, 16, 4)
    k_encode<<<g2, 256>>>();

    dim3 g3(W/16, H/4, B);    // (8, 32, 4)
    k_carafe<<<g3, 256>>>(X, out);
}

// round 13
// speedup vs baseline: 1.2720x; 1.2720x over previous
#include <cuda_runtime.h>
#include <math.h>

// ---------------- problem dims ----------------
#define EPSV 1e-5f
#define B 4
#define C 64           // input channels
#define H 128
#define W 128
#define HW (H*W)       // 16384
#define CMID 64        // compressed channels
#define O 100          // encoder output channels (25 kernels * 4 quadrants)
#define OP 128         // padded O for clean tiling
#define NTAP 9

// ---------------- device scratch (no allocation allowed) ----------------
__device__ float g_M[B*CMID*HW];        // compressed feature map
__device__ float g_E[B*O*HW];           // encoder output (pre-softmax)
__device__ float g_wenc[NTAP*CMID*OP];  // BN-folded, padded, transposed enc weights [tap][cm][o]
__device__ float g_benc[OP];            // folded bias+BN

// ---------------- packed fp32x2 FMA (Blackwell, PTX-only) ----------------
__device__ __forceinline__ void ffma2(float2& d, float2 a, float2 b) {
    asm("fma.rn.f32x2 %0, %1, %2, %0;"
        : "+l"(reinterpret_cast<unsigned long long&>(d))
        : "l"(reinterpret_cast<unsigned long long&>(a)),
          "l"(reinterpret_cast<unsigned long long&>(b)));
}

// =====================================================================
// K0: prep — fold enc BN into weights, pad O 100->128, layout [tap][cm][o]
// =====================================================================
__global__ void k_prep(const float* __restrict__ enc_w, const float* __restrict__ enc_b,
                       const float* __restrict__ eg, const float* __restrict__ ebt,
                       const float* __restrict__ em, const float* __restrict__ ev) {
    int gid = blockIdx.x * blockDim.x + threadIdx.x;
    if (gid < NTAP*CMID*OP) {
        int o   = gid & (OP-1);
        int cm  = (gid >> 7) & 63;
        int tap = gid >> 13;
        float v = 0.f;
        if (o < O) {
            float inv = eg[o] * rsqrtf(ev[o] + EPSV);
            v = enc_w[o*576 + cm*9 + tap] * inv;   // enc_w is [O][CMID][3][3]
        }
        g_wenc[gid] = v;
    }
    if (gid < OP) {
        float v = 0.f;
        if (gid < O) {
            float inv = eg[gid] * rsqrtf(ev[gid] + EPSV);
            v = enc_b[gid]*inv + ebt[gid] - em[gid]*inv;
        }
        g_benc[gid] = v;
    }
}

// =====================================================================
// K1: compress — 1x1 conv (64x64 GEMM per pixel) + BN + ReLU -> g_M
// =====================================================================
__global__ __launch_bounds__(256) void k_compress(
        const float* __restrict__ X, const float* __restrict__ cw,
        const float* __restrict__ cg, const float* __restrict__ cb,
        const float* __restrict__ cmu, const float* __restrict__ cv) {
    __shared__ float sw1[C*CMID];   // [c][cm] transposed + BN folded
    __shared__ float sb1[CMID];
    int tid = threadIdx.x;
    for (int i = tid; i < C*CMID; i += 256) {
        int cmi = i & 63, c = i >> 6;
        float inv = cg[cmi] * rsqrtf(cv[cmi] + EPSV);
        sw1[i] = cw[cmi*C + c] * inv;
    }
    if (tid < CMID) {
        float inv = cg[tid] * rsqrtf(cv[tid] + EPSV);
        sb1[tid] = cb[tid] - cmu[tid]*inv;
    }
    __syncthreads();

    int gid = blockIdx.x * 256 + tid;
    int b = gid >> 14, s = gid & (HW-1);
    const float* xp = X + (size_t)b*C*HW + s;

    float2 acc[CMID/2];
#pragma unroll
    for (int j = 0; j < CMID/2; j++) acc[j] = make_float2(0.f, 0.f);

    for (int c = 0; c < C; c++) {
        float xv = xp[c*HW];
        float2 x2 = make_float2(xv, xv);
        const float2* wr = reinterpret_cast<const float2*>(&sw1[c*CMID]);
#pragma unroll
        for (int j = 0; j < CMID/2; j++) ffma2(acc[j], wr[j], x2);
    }

    float* mp = g_M + (size_t)b*CMID*HW + s;
#pragma unroll
    for (int j = 0; j < CMID/2; j++) {
        mp[(2*j  )*HW] = fmaxf(acc[j].x + sb1[2*j  ], 0.f);
        mp[(2*j+1)*HW] = fmaxf(acc[j].y + sb1[2*j+1], 0.f);
    }
}

// =====================================================================
// K2: encode — 3x3 conv as K=576 GEMM, tile = 8 rows x 16 cols pixels
// Full 64-cm halo tile in smem (one load, 2 syncs total).
// Weights read straight from GMEM via __ldg (L1-resident, warp-broadcast)
// — no per-tap smem reload, no per-tap syncthreads.
// thread = (to 0..15 -> 8 o's as 4 f32x2, tp 0..15 pixel col) x 8 rows
// =====================================================================
#define TH 8
#define TW 16
__global__ __launch_bounds__(256, 2) void k_encode() {
    __shared__ float sM[CMID*10*18];   // 64 ch x (8+2) x (16+2) halo = 46.08 KB

    int tid = threadIdx.x;
    int to = tid >> 4, tp = tid & 15;
    int b   = blockIdx.z;
    int yl0 = blockIdx.y * TH;
    int xl0 = blockIdx.x * TW;

    // load halo tile (zero-pad at borders)
    for (int i = tid; i < CMID*180; i += 256) {
        int cm = i / 180;
        int rem = i - cm*180;
        int rr = rem / 18, cc = rem - rr*18;
        int gy = yl0 + rr - 1, gx = xl0 + cc - 1;
        float v = 0.f;
        if ((unsigned)gy < H && (unsigned)gx < W)
            v = g_M[((size_t)(b*CMID + cm) << 14) + gy*W + gx];
        sM[i] = v;
    }
    __syncthreads();

    float2 acc[4][8];
#pragma unroll
    for (int u = 0; u < 4; u++)
#pragma unroll
        for (int r = 0; r < 8; r++) acc[u][r] = make_float2(0.f, 0.f);

    for (int tap = 0; tap < 9; tap++) {
        int di = tap / 3, dj = tap - di*3;
        int mo = di*18 + dj + tp;
        const float2* wbase = reinterpret_cast<const float2*>(g_wenc + tap*(CMID*OP) + to*8);
#pragma unroll 4
        for (int kk = 0; kk < CMID; kk++) {
            const float* mp = &sM[kk*180 + mo];
            float2 m2[8];
#pragma unroll
            for (int r = 0; r < 8; r++) {
                float v = mp[r*18];
                m2[r] = make_float2(v, v);
            }
            float2 w2[4];
#pragma unroll
            for (int u = 0; u < 4; u++) w2[u] = __ldg(&wbase[kk*(OP/2) + u]);
#pragma unroll
            for (int u = 0; u < 4; u++)
#pragma unroll
                for (int r = 0; r < 8; r++) ffma2(acc[u][r], w2[u], m2[r]);
        }
    }

    // epilogue: add folded bias, store (skip padded o >= 100)
#pragma unroll
    for (int u = 0; u < 4; u++) {
        int o0 = to*8 + 2*u, o1 = o0 + 1;
        float b0 = g_benc[o0], b1 = g_benc[o1];
#pragma unroll
        for (int r = 0; r < 8; r++) {
            int row = yl0 + r;
            if (o0 < O) g_E[((size_t)(b*O + o0) << 14) + row*W + xl0 + tp] = acc[u][r].x + b0;
            if (o1 < O) g_E[((size_t)(b*O + o1) << 14) + row*W + xl0 + tp] = acc[u][r].y + b1;
        }
    }
}

// =====================================================================
// K3: pixel-shuffle + softmax + CARAFE gather (fused)
// dilation==scale==2 collapses the 25 taps onto the low-res 5x5 grid.
// block tile: 4 x 16 low-res pixels.
// Phase A: stage raw E for the 64 pixels into smem (coalesced), softmax
//          in-place (thread = pixel x quadrant).
// Phase B: thread = (pixel, q=2dy+dx). Its 25 weights are channel-
//          invariant -> pre-duplicated into 25 f32x2 REGISTERS once.
//          X tile staged channel-PAIR interleaved so each x operand is a
//          natural LDS.64 float2; f32x2 pairs adjacent channels. Zero
//          per-tap MOV duplication in the hot loop.
// =====================================================================
#define SWP 104
__global__ __launch_bounds__(256) void k_carafe(const float* __restrict__ X,
                                                float* __restrict__ out) {
    __shared__ float sw[64*SWP];     // per-pixel weights [pix][o]      (26.6 KB)
    __shared__ float sx[16*320];     // 16 ch-pairs x 8x20 halo x2 intl (20.5 KB)

    int tid = threadIdx.x;
    int b   = blockIdx.z;
    int yl0 = blockIdx.y * 4;
    int xl0 = blockIdx.x * 16;

    // ---- Phase A: stage E (coalesced over pixels), softmax in smem ----
    for (int j = tid; j < 64*O; j += 256) {
        int o = j >> 6, pix = j & 63;
        int row = pix >> 4, col = pix & 15;
        sw[pix*SWP + o] = g_E[((size_t)(b*O + o) << 14) + (yl0 + row)*W + xl0 + col];
    }
    __syncthreads();
    {
        int spix = tid >> 2, q = tid & 3;
        float* wp = &sw[spix*SWP + q];
        float e[25];
        float mx = -1e30f;
#pragma unroll
        for (int k = 0; k < 25; k++) { e[k] = wp[4*k]; mx = fmaxf(mx, e[k]); }
        float s = 0.f;
#pragma unroll
        for (int k = 0; k < 25; k++) { e[k] = expf(e[k] - mx); s += e[k]; }
        float inv = 1.f / s;
#pragma unroll
        for (int k = 0; k < 25; k++) wp[4*k] = e[k]*inv;
    }
    __syncthreads();

    // ---- per-thread weights, duplicated into f32x2 once ----
    int pix = tid & 63;
    int q   = tid >> 6;            // q = 2*dy + dx
    int dy  = q >> 1, dx = q & 1;
    int rloc = pix >> 4, col = pix & 15;

    float2 wv[25];
#pragma unroll
    for (int k = 0; k < 25; k++) {
        float v = sw[pix*SWP + 4*k + q];
        wv[k] = make_float2(v, v);
    }

    int oy = 2*(yl0 + rloc) + dy;
    int ox = 2*(xl0 + col) + dx;
    float* outp = out + ((size_t)b*C*(2*H) + oy)*(2*W) + ox;

    // ---- Phase B: channels in 2 halves of 32 (16 interleaved pairs) ----
    for (int half = 0; half < 2; half++) {
        __syncthreads();
        for (int i = tid; i < 32*160; i += 256) {
            int cL = i / 160;
            int sp = i - cL*160;
            int rr = sp / 20, cc = sp - rr*20;
            int gy = yl0 + rr - 2, gx = xl0 + cc - 2;
            float v = 0.f;
            if ((unsigned)gy < H && (unsigned)gx < W)
                v = X[((size_t)(b*C + half*32 + cL) << 14) + gy*W + gx];
            sx[(cL >> 1)*320 + sp*2 + (cL & 1)] = v;
        }
        __syncthreads();

#pragma unroll 2
        for (int cp = 0; cp < 16; cp++) {
            const float2* sxp = reinterpret_cast<const float2*>(
                &sx[cp*320 + (rloc*20 + col)*2]);
            float2 a = make_float2(0.f, 0.f);
#pragma unroll
            for (int i5 = 0; i5 < 5; i5++)
#pragma unroll
                for (int j5 = 0; j5 < 5; j5++)
                    ffma2(a, sxp[i5*20 + j5], wv[i5*5 + j5]);

            int c0 = (half*16 + cp)*2;
            outp[(size_t)c0    *(4*HW)] = a.x;
            outp[(size_t)(c0+1)*(4*HW)] = a.y;
        }
    }
}

// =====================================================================
// launch
// =====================================================================
extern "C" void kernel_launch(void* const* d_in, const int* in_sizes, int n_in,
                              void* d_out, int out_size) {
    const float* X      = (const float*)d_in[0];
    const float* comp_w = (const float*)d_in[1];
    const float* comp_g = (const float*)d_in[2];
    const float* comp_b = (const float*)d_in[3];
    const float* comp_m = (const float*)d_in[4];
    const float* comp_v = (const float*)d_in[5];
    const float* enc_w  = (const float*)d_in[6];
    const float* enc_b  = (const float*)d_in[7];
    const float* enc_g  = (const float*)d_in[8];
    const float* enc_bt = (const float*)d_in[9];
    const float* enc_m  = (const float*)d_in[10];
    const float* enc_v  = (const float*)d_in[11];
    float* out = (float*)d_out;

    k_prep<<<(NTAP*CMID*OP + 255)/256, 256>>>(enc_w, enc_b, enc_g, enc_bt, enc_m, enc_v);
    k_compress<<<(B*HW)/256, 256>>>(X, comp_w, comp_g, comp_b, comp_m, comp_v);

    dim3 g2(W/TW, H/TH, B);   // (8, 16, 4)
    k_encode<<<g2, 256>>>();

    dim3 g3(W/16, H/4, B);    // (8, 32, 4)
    k_carafe<<<g3, 256>>>(X, out);
}

// round 14
// speedup vs baseline: 1.3408x; 1.0541x over previous
#include <cuda_runtime.h>
#include <math.h>

// ---------------- problem dims ----------------
#define EPSV 1e-5f
#define B 4
#define C 64           // input channels
#define H 128
#define W 128
#define HW (H*W)       // 16384
#define CMID 64        // compressed channels
#define O 100          // encoder output channels (25 kernels * 4 quadrants)
#define OP 128         // padded O for clean tiling
#define NTAP 9

// ---------------- device scratch (no allocation allowed) ----------------
__device__ float g_M[B*CMID*HW];        // compressed feature map
__device__ float g_E[B*O*HW];           // encoder output (pre-softmax)
__device__ float g_wenc[NTAP*CMID*OP];  // BN-folded, padded, transposed enc weights [tap][cm][o]
__device__ float g_benc[OP];            // folded bias+BN

// ---------------- packed fp32x2 FMA (Blackwell, PTX-only) ----------------
__device__ __forceinline__ void ffma2(float2& d, float2 a, float2 b) {
    asm("fma.rn.f32x2 %0, %1, %2, %0;"
        : "+l"(reinterpret_cast<unsigned long long&>(d))
        : "l"(reinterpret_cast<unsigned long long&>(a)),
          "l"(reinterpret_cast<unsigned long long&>(b)));
}

// =====================================================================
// K0: prep — fold enc BN into weights, pad O 100->128, layout [tap][cm][o]
// =====================================================================
__global__ void k_prep(const float* __restrict__ enc_w, const float* __restrict__ enc_b,
                       const float* __restrict__ eg, const float* __restrict__ ebt,
                       const float* __restrict__ em, const float* __restrict__ ev) {
    int gid = blockIdx.x * blockDim.x + threadIdx.x;
    if (gid < NTAP*CMID*OP) {
        int o   = gid & (OP-1);
        int cm  = (gid >> 7) & 63;
        int tap = gid >> 13;
        float v = 0.f;
        if (o < O) {
            float inv = eg[o] * rsqrtf(ev[o] + EPSV);
            v = enc_w[o*576 + cm*9 + tap] * inv;   // enc_w is [O][CMID][3][3]
        }
        g_wenc[gid] = v;
    }
    if (gid < OP) {
        float v = 0.f;
        if (gid < O) {
            float inv = eg[gid] * rsqrtf(ev[gid] + EPSV);
            v = enc_b[gid]*inv + ebt[gid] - em[gid]*inv;
        }
        g_benc[gid] = v;
    }
}

// =====================================================================
// K1: compress — 1x1 conv (64x64 GEMM per pixel) + BN + ReLU -> g_M
// =====================================================================
__global__ __launch_bounds__(256) void k_compress(
        const float* __restrict__ X, const float* __restrict__ cw,
        const float* __restrict__ cg, const float* __restrict__ cb,
        const float* __restrict__ cmu, const float* __restrict__ cv) {
    __shared__ float sw1[C*CMID];   // [c][cm] transposed + BN folded
    __shared__ float sb1[CMID];
    int tid = threadIdx.x;
    for (int i = tid; i < C*CMID; i += 256) {
        int cmi = i & 63, c = i >> 6;
        float inv = cg[cmi] * rsqrtf(cv[cmi] + EPSV);
        sw1[i] = cw[cmi*C + c] * inv;
    }
    if (tid < CMID) {
        float inv = cg[tid] * rsqrtf(cv[tid] + EPSV);
        sb1[tid] = cb[tid] - cmu[tid]*inv;
    }
    __syncthreads();

    int gid = blockIdx.x * 256 + tid;
    int b = gid >> 14, s = gid & (HW-1);
    const float* xp = X + (size_t)b*C*HW + s;

    float2 acc[CMID/2];
#pragma unroll
    for (int j = 0; j < CMID/2; j++) acc[j] = make_float2(0.f, 0.f);

    for (int c = 0; c < C; c++) {
        float xv = xp[c*HW];
        float2 x2 = make_float2(xv, xv);
        const float2* wr = reinterpret_cast<const float2*>(&sw1[c*CMID]);
#pragma unroll
        for (int j = 0; j < CMID/2; j++) ffma2(acc[j], wr[j], x2);
    }

    float* mp = g_M + (size_t)b*CMID*HW + s;
#pragma unroll
    for (int j = 0; j < CMID/2; j++) {
        mp[(2*j  )*HW] = fmaxf(acc[j].x + sb1[2*j  ], 0.f);
        mp[(2*j+1)*HW] = fmaxf(acc[j].y + sb1[2*j+1], 0.f);
    }
}

// =====================================================================
// K2: encode — 3x3 conv as K=576 GEMM, tile = 8 rows x 16 cols pixels
// Full 64-cm halo tile in smem. Weights from GMEM via __ldg with an
// explicit ping-pong register double-buffer so the next kk's weight
// loads issue before the current kk's 32 FFMA2s (hides L1/L2 latency).
// =====================================================================
#define TH 8
#define TW 16
__global__ __launch_bounds__(256, 2) void k_encode() {
    __shared__ float sM[CMID*10*18];   // 64 ch x (8+2) x (16+2) halo = 46.08 KB

    int tid = threadIdx.x;
    int to = tid >> 4, tp = tid & 15;
    int b   = blockIdx.z;
    int yl0 = blockIdx.y * TH;
    int xl0 = blockIdx.x * TW;

    // load halo tile (zero-pad at borders)
    for (int i = tid; i < CMID*180; i += 256) {
        int cm = i / 180;
        int rem = i - cm*180;
        int rr = rem / 18, cc = rem - rr*18;
        int gy = yl0 + rr - 1, gx = xl0 + cc - 1;
        float v = 0.f;
        if ((unsigned)gy < H && (unsigned)gx < W)
            v = g_M[((size_t)(b*CMID + cm) << 14) + gy*W + gx];
        sM[i] = v;
    }
    __syncthreads();

    float2 acc[4][8];
#pragma unroll
    for (int u = 0; u < 4; u++)
#pragma unroll
        for (int r = 0; r < 8; r++) acc[u][r] = make_float2(0.f, 0.f);

    for (int tap = 0; tap < 9; tap++) {
        int di = tap / 3, dj = tap - di*3;
        int mo = di*18 + dj + tp;
        const float2* wbase = reinterpret_cast<const float2*>(g_wenc + tap*(CMID*OP) + to*8);

        // prime the weight double-buffer for kk=0
        float2 wbuf[2][4];
#pragma unroll
        for (int u = 0; u < 4; u++) wbuf[0][u] = __ldg(&wbase[u]);

#pragma unroll 2
        for (int kk = 0; kk < CMID; kk++) {
            int cur = kk & 1, nxt = cur ^ 1;
            // prefetch weights for kk+1 (OOB-safe: clamp to last row)
            int kn = (kk < CMID-1) ? kk+1 : kk;
#pragma unroll
            for (int u = 0; u < 4; u++) wbuf[nxt][u] = __ldg(&wbase[kn*(OP/2) + u]);

            const float* mp = &sM[kk*180 + mo];
            float2 m2[8];
#pragma unroll
            for (int r = 0; r < 8; r++) {
                float v = mp[r*18];
                m2[r] = make_float2(v, v);
            }
#pragma unroll
            for (int u = 0; u < 4; u++)
#pragma unroll
                for (int r = 0; r < 8; r++) ffma2(acc[u][r], wbuf[cur][u], m2[r]);
        }
    }

    // epilogue: add folded bias, store (skip padded o >= 100)
#pragma unroll
    for (int u = 0; u < 4; u++) {
        int o0 = to*8 + 2*u, o1 = o0 + 1;
        float b0 = g_benc[o0], b1 = g_benc[o1];
#pragma unroll
        for (int r = 0; r < 8; r++) {
            int row = yl0 + r;
            if (o0 < O) g_E[((size_t)(b*O + o0) << 14) + row*W + xl0 + tp] = acc[u][r].x + b0;
            if (o1 < O) g_E[((size_t)(b*O + o1) << 14) + row*W + xl0 + tp] = acc[u][r].y + b1;
        }
    }
}

// =====================================================================
// K3: pixel-shuffle + softmax + CARAFE gather (fused), v3
// Thread = (pixel, channel-group): each thread computes ALL 4 quadrants
// for 4 channel-pairs per half -> every x LDS.64 feeds 4 FFMA2 (was 1).
// Weights transposed to [o][pix] in smem: lane-consecutive, conflict-free.
// Per tap: 4 LDS.32 (w) + 4 dup + 4 LDS.64 (x pairs) + 16 FFMA2.
// =====================================================================
__global__ __launch_bounds__(256) void k_carafe(const float* __restrict__ X,
                                                float* __restrict__ out) {
    __shared__ float sw2[O*64];      // weights transposed [o][pix]   (25.6 KB)
    __shared__ float sx[16*320];     // 16 ch-pairs x 8x20 halo, pair-interleaved (20.5 KB)

    int tid = threadIdx.x;
    int b   = blockIdx.z;
    int yl0 = blockIdx.y * 4;
    int xl0 = blockIdx.x * 16;

    // ---- Phase A: stage E transposed (coalesced both sides), softmax ----
    for (int j = tid; j < 64*O; j += 256) {
        int o = j >> 6, pix = j & 63;
        int row = pix >> 4, col = pix & 15;
        sw2[o*64 + pix] = g_E[((size_t)(b*O + o) << 14) + (yl0 + row)*W + xl0 + col];
    }
    __syncthreads();
    {
        int spix = tid >> 2, q = tid & 3;
        float* wp = &sw2[q*64 + spix];
        float e[25];
        float mx = -1e30f;
#pragma unroll
        for (int k = 0; k < 25; k++) { e[k] = wp[k*256]; mx = fmaxf(mx, e[k]); }
        float s = 0.f;
#pragma unroll
        for (int k = 0; k < 25; k++) { e[k] = expf(e[k] - mx); s += e[k]; }
        float inv = 1.f / s;
#pragma unroll
        for (int k = 0; k < 25; k++) wp[k*256] = e[k]*inv;
    }

    int pix = tid & 63;
    int grp = tid >> 6;             // channel group 0..3 (4 pairs each per half)
    int rloc = pix >> 4, col = pix & 15;

    const float* outb = out + (size_t)b*C*(4*HW);
    int oy = 2*(yl0 + rloc);
    int ox = 2*(xl0 + col);

    // ---- Phase B: channels in 2 halves of 32 (16 interleaved pairs) ----
    for (int half = 0; half < 2; half++) {
        __syncthreads();
        // stage X halo: one thread writes both channels of a pair (STS.64)
        for (int i = tid; i < 16*160; i += 256) {
            int cp = i / 160;
            int sp = i - cp*160;
            int rr = sp / 20, cc = sp - rr*20;
            int gy = yl0 + rr - 2, gx = xl0 + cc - 2;
            float2 v = make_float2(0.f, 0.f);
            if ((unsigned)gy < H && (unsigned)gx < W) {
                const float* xp = X + ((size_t)(b*C + half*32 + 2*cp) << 14) + gy*W + gx;
                v.x = xp[0];
                v.y = xp[HW];
            }
            *reinterpret_cast<float2*>(&sx[cp*320 + sp*2]) = v;
        }
        __syncthreads();

        float2 acc[4][4];   // [pair][quadrant]
#pragma unroll
        for (int p = 0; p < 4; p++)
#pragma unroll
            for (int q = 0; q < 4; q++) acc[p][q] = make_float2(0.f, 0.f);

#pragma unroll
        for (int i5 = 0; i5 < 5; i5++)
#pragma unroll
            for (int j5 = 0; j5 < 5; j5++) {
                int k = i5*5 + j5;
                // 4 quadrant weights for this (pixel, tap): lane-consecutive LDS.32
                float2 wq[4];
#pragma unroll
                for (int q = 0; q < 4; q++) {
                    float wv = sw2[(4*k + q)*64 + pix];
                    wq[q] = make_float2(wv, wv);
                }
                int xoff = ((rloc + i5)*20 + col + j5)*2;
#pragma unroll
                for (int p = 0; p < 4; p++) {
                    float2 x2 = *reinterpret_cast<const float2*>(
                        &sx[(grp*4 + p)*320 + xoff]);
#pragma unroll
                    for (int q = 0; q < 4; q++) ffma2(acc[p][q], x2, wq[q]);
                }
            }

        // store: pair (dx0,dx1) as STG.64 (full sectors)
#pragma unroll
        for (int p = 0; p < 4; p++) {
            int c0 = (half*16 + grp*4 + p)*2;
#pragma unroll
            for (int dy = 0; dy < 2; dy++) {
                float* op = (float*)outb + ((size_t)c0*(2*H) + oy + dy)*(2*W) + ox;
                *reinterpret_cast<float2*>(op) =
                    make_float2(acc[p][2*dy].x, acc[p][2*dy+1].x);
                *reinterpret_cast<float2*>(op + 4*HW) =
                    make_float2(acc[p][2*dy].y, acc[p][2*dy+1].y);
            }
        }
    }
}

// =====================================================================
// launch
// =====================================================================
extern "C" void kernel_launch(void* const* d_in, const int* in_sizes, int n_in,
                              void* d_out, int out_size) {
    const float* X      = (const float*)d_in[0];
    const float* comp_w = (const float*)d_in[1];
    const float* comp_g = (const float*)d_in[2];
    const float* comp_b = (const float*)d_in[3];
    const float* comp_m = (const float*)d_in[4];
    const float* comp_v = (const float*)d_in[5];
    const float* enc_w  = (const float*)d_in[6];
    const float* enc_b  = (const float*)d_in[7];
    const float* enc_g  = (const float*)d_in[8];
    const float* enc_bt = (const float*)d_in[9];
    const float* enc_m  = (const float*)d_in[10];
    const float* enc_v  = (const float*)d_in[11];
    float* out = (float*)d_out;

    k_prep<<<(NTAP*CMID*OP + 255)/256, 256>>>(enc_w, enc_b, enc_g, enc_bt, enc_m, enc_v);
    k_compress<<<(B*HW)/256, 256>>>(X, comp_w, comp_g, comp_b, comp_m, comp_v);

    dim3 g2(W/TW, H/TH, B);   // (8, 16, 4)
    k_encode<<<g2, 256>>>();

    dim3 g3(W/16, H/4, B);    // (8, 32, 4)
    k_carafe<<<g3, 256>>>(X, out);
}

// round 15
// speedup vs baseline: 1.3457x; 1.0037x over previous
#include <cuda_runtime.h>
#include <math.h>

// ---------------- problem dims ----------------
#define EPSV 1e-5f
#define B 4
#define C 64           // input channels
#define H 128
#define W 128
#define HW (H*W)       // 16384
#define CMID 64        // compressed channels
#define O 100          // encoder output channels (25 kernels * 4 quadrants)
#define OP 128         // padded O for clean tiling
#define NTAP 9

// ---------------- device scratch (no allocation allowed) ----------------
__device__ float g_M[B*CMID*HW];        // compressed feature map
__device__ float g_E[B*O*HW];           // encoder output (pre-softmax)
__device__ float g_wenc[NTAP*CMID*OP];  // BN-folded, padded, transposed enc weights [tap][cm][o]
__device__ float g_benc[OP];            // folded bias+BN

// ---------------- packed fp32x2 FMA (Blackwell, PTX-only) ----------------
__device__ __forceinline__ void ffma2(float2& d, float2 a, float2 b) {
    asm("fma.rn.f32x2 %0, %1, %2, %0;"
        : "+l"(reinterpret_cast<unsigned long long&>(d))
        : "l"(reinterpret_cast<unsigned long long&>(a)),
          "l"(reinterpret_cast<unsigned long long&>(b)));
}

// =====================================================================
// K0: prep — fold enc BN into weights, pad O 100->128, layout [tap][cm][o]
// =====================================================================
__global__ void k_prep(const float* __restrict__ enc_w, const float* __restrict__ enc_b,
                       const float* __restrict__ eg, const float* __restrict__ ebt,
                       const float* __restrict__ em, const float* __restrict__ ev) {
    int gid = blockIdx.x * blockDim.x + threadIdx.x;
    if (gid < NTAP*CMID*OP) {
        int o   = gid & (OP-1);
        int cm  = (gid >> 7) & 63;
        int tap = gid >> 13;
        float v = 0.f;
        if (o < O) {
            float inv = eg[o] * rsqrtf(ev[o] + EPSV);
            v = enc_w[o*576 + cm*9 + tap] * inv;   // enc_w is [O][CMID][3][3]
        }
        g_wenc[gid] = v;
    }
    if (gid < OP) {
        float v = 0.f;
        if (gid < O) {
            float inv = eg[gid] * rsqrtf(ev[gid] + EPSV);
            v = enc_b[gid]*inv + ebt[gid] - em[gid]*inv;
        }
        g_benc[gid] = v;
    }
}

// =====================================================================
// K1: compress — 1x1 conv (64x64 GEMM per pixel) + BN + ReLU -> g_M
// =====================================================================
__global__ __launch_bounds__(256) void k_compress(
        const float* __restrict__ X, const float* __restrict__ cw,
        const float* __restrict__ cg, const float* __restrict__ cb,
        const float* __restrict__ cmu, const float* __restrict__ cv) {
    __shared__ float sw1[C*CMID];   // [c][cm] transposed + BN folded
    __shared__ float sb1[CMID];
    int tid = threadIdx.x;
    for (int i = tid; i < C*CMID; i += 256) {
        int cmi = i & 63, c = i >> 6;
        float inv = cg[cmi] * rsqrtf(cv[cmi] + EPSV);
        sw1[i] = cw[cmi*C + c] * inv;
    }
    if (tid < CMID) {
        float inv = cg[tid] * rsqrtf(cv[tid] + EPSV);
        sb1[tid] = cb[tid] - cmu[tid]*inv;
    }
    __syncthreads();

    int gid = blockIdx.x * 256 + tid;
    int b = gid >> 14, s = gid & (HW-1);
    const float* xp = X + (size_t)b*C*HW + s;

    float2 acc[CMID/2];
#pragma unroll
    for (int j = 0; j < CMID/2; j++) acc[j] = make_float2(0.f, 0.f);

    for (int c = 0; c < C; c++) {
        float xv = xp[c*HW];
        float2 x2 = make_float2(xv, xv);
        const float2* wr = reinterpret_cast<const float2*>(&sw1[c*CMID]);
#pragma unroll
        for (int j = 0; j < CMID/2; j++) ffma2(acc[j], wr[j], x2);
    }

    float* mp = g_M + (size_t)b*CMID*HW + s;
#pragma unroll
    for (int j = 0; j < CMID/2; j++) {
        mp[(2*j  )*HW] = fmaxf(acc[j].x + sb1[2*j  ], 0.f);
        mp[(2*j+1)*HW] = fmaxf(acc[j].y + sb1[2*j+1], 0.f);
    }
}

// =====================================================================
// K2: encode — 3x3 conv as K=576 GEMM, tile = 8 rows x 16 cols pixels
// Full 64-cm halo tile in smem. Weights from GMEM via __ldg with an
// explicit ping-pong register double-buffer so the next kk's weight
// loads issue before the current kk's 32 FFMA2s (hides L1/L2 latency).
// =====================================================================
#define TH 8
#define TW 16
__global__ __launch_bounds__(256, 2) void k_encode() {
    __shared__ float sM[CMID*10*18];   // 64 ch x (8+2) x (16+2) halo = 46.08 KB

    int tid = threadIdx.x;
    int to = tid >> 4, tp = tid & 15;
    int b   = blockIdx.z;
    int yl0 = blockIdx.y * TH;
    int xl0 = blockIdx.x * TW;

    // load halo tile (zero-pad at borders)
    for (int i = tid; i < CMID*180; i += 256) {
        int cm = i / 180;
        int rem = i - cm*180;
        int rr = rem / 18, cc = rem - rr*18;
        int gy = yl0 + rr - 1, gx = xl0 + cc - 1;
        float v = 0.f;
        if ((unsigned)gy < H && (unsigned)gx < W)
            v = g_M[((size_t)(b*CMID + cm) << 14) + gy*W + gx];
        sM[i] = v;
    }
    __syncthreads();

    float2 acc[4][8];
#pragma unroll
    for (int u = 0; u < 4; u++)
#pragma unroll
        for (int r = 0; r < 8; r++) acc[u][r] = make_float2(0.f, 0.f);

    for (int tap = 0; tap < 9; tap++) {
        int di = tap / 3, dj = tap - di*3;
        int mo = di*18 + dj + tp;
        const float2* wbase = reinterpret_cast<const float2*>(g_wenc + tap*(CMID*OP) + to*8);

        // prime the weight double-buffer for kk=0
        float2 wbuf[2][4];
#pragma unroll
        for (int u = 0; u < 4; u++) wbuf[0][u] = __ldg(&wbase[u]);

#pragma unroll 2
        for (int kk = 0; kk < CMID; kk++) {
            int cur = kk & 1, nxt = cur ^ 1;
            // prefetch weights for kk+1 (OOB-safe: clamp to last row)
            int kn = (kk < CMID-1) ? kk+1 : kk;
#pragma unroll
            for (int u = 0; u < 4; u++) wbuf[nxt][u] = __ldg(&wbase[kn*(OP/2) + u]);

            const float* mp = &sM[kk*180 + mo];
            float2 m2[8];
#pragma unroll
            for (int r = 0; r < 8; r++) {
                float v = mp[r*18];
                m2[r] = make_float2(v, v);
            }
#pragma unroll
            for (int u = 0; u < 4; u++)
#pragma unroll
                for (int r = 0; r < 8; r++) ffma2(acc[u][r], wbuf[cur][u], m2[r]);
        }
    }

    // epilogue: add folded bias, store (skip padded o >= 100)
#pragma unroll
    for (int u = 0; u < 4; u++) {
        int o0 = to*8 + 2*u, o1 = o0 + 1;
        float b0 = g_benc[o0], b1 = g_benc[o1];
#pragma unroll
        for (int r = 0; r < 8; r++) {
            int row = yl0 + r;
            if (o0 < O) g_E[((size_t)(b*O + o0) << 14) + row*W + xl0 + tp] = acc[u][r].x + b0;
            if (o1 < O) g_E[((size_t)(b*O + o1) << 14) + row*W + xl0 + tp] = acc[u][r].y + b1;
        }
    }
}

// =====================================================================
// K3: pixel-shuffle + softmax + CARAFE gather (fused), v3
// Thread = (pixel, channel-group): each thread computes ALL 4 quadrants
// for 4 channel-pairs per half -> every x LDS.64 feeds 4 FFMA2 (was 1).
// Weights transposed to [o][pix] in smem: lane-consecutive, conflict-free.
// Per tap: 4 LDS.32 (w) + 4 dup + 4 LDS.64 (x pairs) + 16 FFMA2.
// =====================================================================
__global__ __launch_bounds__(256) void k_carafe(const float* __restrict__ X,
                                                float* __restrict__ out) {
    __shared__ float sw2[O*64];      // weights transposed [o][pix]   (25.6 KB)
    __shared__ float sx[16*320];     // 16 ch-pairs x 8x20 halo, pair-interleaved (20.5 KB)

    int tid = threadIdx.x;
    int b   = blockIdx.z;
    int yl0 = blockIdx.y * 4;
    int xl0 = blockIdx.x * 16;

    // ---- Phase A: stage E transposed (coalesced both sides), softmax ----
    for (int j = tid; j < 64*O; j += 256) {
        int o = j >> 6, pix = j & 63;
        int row = pix >> 4, col = pix & 15;
        sw2[o*64 + pix] = g_E[((size_t)(b*O + o) << 14) + (yl0 + row)*W + xl0 + col];
    }
    __syncthreads();
    {
        int spix = tid >> 2, q = tid & 3;
        float* wp = &sw2[q*64 + spix];
        float e[25];
        float mx = -1e30f;
#pragma unroll
        for (int k = 0; k < 25; k++) { e[k] = wp[k*256]; mx = fmaxf(mx, e[k]); }
        float s = 0.f;
#pragma unroll
        for (int k = 0; k < 25; k++) { e[k] = expf(e[k] - mx); s += e[k]; }
        float inv = 1.f / s;
#pragma unroll
        for (int k = 0; k < 25; k++) wp[k*256] = e[k]*inv;
    }

    int pix = tid & 63;
    int grp = tid >> 6;             // channel group 0..3 (4 pairs each per half)
    int rloc = pix >> 4, col = pix & 15;

    const float* outb = out + (size_t)b*C*(4*HW);
    int oy = 2*(yl0 + rloc);
    int ox = 2*(xl0 + col);

    // ---- Phase B: channels in 2 halves of 32 (16 interleaved pairs) ----
    for (int half = 0; half < 2; half++) {
        __syncthreads();
        // stage X halo: one thread writes both channels of a pair (STS.64)
        for (int i = tid; i < 16*160; i += 256) {
            int cp = i / 160;
            int sp = i - cp*160;
            int rr = sp / 20, cc = sp - rr*20;
            int gy = yl0 + rr - 2, gx = xl0 + cc - 2;
            float2 v = make_float2(0.f, 0.f);
            if ((unsigned)gy < H && (unsigned)gx < W) {
                const float* xp = X + ((size_t)(b*C + half*32 + 2*cp) << 14) + gy*W + gx;
                v.x = xp[0];
                v.y = xp[HW];
            }
            *reinterpret_cast<float2*>(&sx[cp*320 + sp*2]) = v;
        }
        __syncthreads();

        float2 acc[4][4];   // [pair][quadrant]
#pragma unroll
        for (int p = 0; p < 4; p++)
#pragma unroll
            for (int q = 0; q < 4; q++) acc[p][q] = make_float2(0.f, 0.f);

#pragma unroll
        for (int i5 = 0; i5 < 5; i5++)
#pragma unroll
            for (int j5 = 0; j5 < 5; j5++) {
                int k = i5*5 + j5;
                // 4 quadrant weights for this (pixel, tap): lane-consecutive LDS.32
                float2 wq[4];
#pragma unroll
                for (int q = 0; q < 4; q++) {
                    float wv = sw2[(4*k + q)*64 + pix];
                    wq[q] = make_float2(wv, wv);
                }
                int xoff = ((rloc + i5)*20 + col + j5)*2;
#pragma unroll
                for (int p = 0; p < 4; p++) {
                    float2 x2 = *reinterpret_cast<const float2*>(
                        &sx[(grp*4 + p)*320 + xoff]);
#pragma unroll
                    for (int q = 0; q < 4; q++) ffma2(acc[p][q], x2, wq[q]);
                }
            }

        // store: pair (dx0,dx1) as STG.64 (full sectors)
#pragma unroll
        for (int p = 0; p < 4; p++) {
            int c0 = (half*16 + grp*4 + p)*2;
#pragma unroll
            for (int dy = 0; dy < 2; dy++) {
                float* op = (float*)outb + ((size_t)c0*(2*H) + oy + dy)*(2*W) + ox;
                *reinterpret_cast<float2*>(op) =
                    make_float2(acc[p][2*dy].x, acc[p][2*dy+1].x);
                *reinterpret_cast<float2*>(op + 4*HW) =
                    make_float2(acc[p][2*dy].y, acc[p][2*dy+1].y);
            }
        }
    }
}

// =====================================================================
// launch
// =====================================================================
extern "C" void kernel_launch(void* const* d_in, const int* in_sizes, int n_in,
                              void* d_out, int out_size) {
    const float* X      = (const float*)d_in[0];
    const float* comp_w = (const float*)d_in[1];
    const float* comp_g = (const float*)d_in[2];
    const float* comp_b = (const float*)d_in[3];
    const float* comp_m = (const float*)d_in[4];
    const float* comp_v = (const float*)d_in[5];
    const float* enc_w  = (const float*)d_in[6];
    const float* enc_b  = (const float*)d_in[7];
    const float* enc_g  = (const float*)d_in[8];
    const float* enc_bt = (const float*)d_in[9];
    const float* enc_m  = (const float*)d_in[10];
    const float* enc_v  = (const float*)d_in[11];
    float* out = (float*)d_out;

    k_prep<<<(NTAP*CMID*OP + 255)/256, 256>>>(enc_w, enc_b, enc_g, enc_bt, enc_m, enc_v);
    k_compress<<<(B*HW)/256, 256>>>(X, comp_w, comp_g, comp_b, comp_m, comp_v);

    dim3 g2(W/TW, H/TH, B);   // (8, 16, 4)
    k_encode<<<g2, 256>>>();

    dim3 g3(W/16, H/4, B);    // (8, 32, 4)
    k_carafe<<<g3, 256>>>(X, out);
}